// round 16
// baseline (speedup 1.0000x reference)
#include <cuda_runtime.h>
#include <cuda_fp16.h>
#include <cstdint>

// ---------------- problem constants ----------------
#define BATCH   2048
#define NATOM   96
#define NIN     128
#define NHID    64
#define LOG2E   1.4426950408889634f
#define LN2     0.6931471805599453f

// CTA-shared fp16 tile: 96 rows x (256B data + 16B pad) = 272B stride, bit-4 XOR swizzle
#define ROWB   272
#define TILEB  (NATOM * ROWB)      // 26112 B

// ---------------- precomputed W1 fp16 image (B-fragment layout) ----------------
// uint2 index = (nt*8 + kt)*32 + lane ; .x = b0 (k pair, khalf 0), .y = b1 (khalf 1)
__device__ __align__(16) uint2 g_wh[2048];   // 16 KB, L1/L2-resident

__global__ void prep_w_kernel(const float* __restrict__ W1) {
    int idx = blockIdx.x * blockDim.x + threadIdx.x;
    if (idx >= NIN * NHID) return;
    int k = idx >> 6;          // 0..127
    int n = idx & 63;          // 0..63
    __half h = __float2half_rn(W1[idx]);
    int nt = n >> 3, g = n & 7;
    int kt = k >> 4, kl = k & 15;
    int tg = (kl >> 1) & 3, br = kl >> 3, odd = kl & 1;
    uint32_t off = (uint32_t)((((nt * 8 + kt) * 32 + (g * 4 + tg)) * 8) + br * 4 + odd * 2);
    *reinterpret_cast<__half*>(reinterpret_cast<unsigned char*>(g_wh) + off) = h;
}

// ---------------- device helpers ----------------
__device__ __forceinline__ void mma_f16(float* c, const uint32_t* a, const uint32_t* b) {
    asm volatile(
        "mma.sync.aligned.m16n8k16.row.col.f32.f16.f16.f32 "
        "{%0,%1,%2,%3}, {%4,%5,%6,%7}, {%8,%9}, {%0,%1,%2,%3};"
        : "+f"(c[0]), "+f"(c[1]), "+f"(c[2]), "+f"(c[3])
        : "r"(a[0]), "r"(a[1]), "r"(a[2]), "r"(a[3]), "r"(b[0]), "r"(b[1]));
}

__device__ __forceinline__ void ldsm_x4(uint32_t* a, uint32_t saddr) {
    asm volatile("ldmatrix.sync.aligned.m8n8.x4.shared.b16 {%0,%1,%2,%3}, [%4];"
        : "=r"(a[0]), "=r"(a[1]), "=r"(a[2]), "=r"(a[3]) : "r"(saddr));
}

__device__ __forceinline__ float ex2f(float x) {
    float r; asm("ex2.approx.f32 %0, %1;" : "=f"(r) : "f"(x)); return r;
}
__device__ __forceinline__ float lg2f(float x) {
    float r; asm("lg2.approx.f32 %0, %1;" : "=f"(r) : "f"(x)); return r;
}

// ---------------- main fused kernel: one CTA (6 warps) per batch sample ----------------
// R11's compute core (fp16 SMEM tile + ldmatrix, best measured at 25.3us) with the
// tile promoted to CTA-SHARED and N split across warp pairs:
//   warp w: rg=w>>1 owns rows [32rg,32rg+32); cg=w&1 owns cols [32cg,32cg+32).
// acc = 32 regs -> 18 warps/SM (vs R11's 15) with no spill; fill per warp halves
// (16 rows); GMEM bytes unchanged (tile shared); only cheap LDSM reads duplicate.
// Epilogue MUFU work per thread halves; lean lg2-space ssp from R15 kept.
__global__ void __launch_bounds__(192, 3)
atomwise_kernel(const float* __restrict__ rep,
                const int*   __restrict__ atomic_numbers,
                const float* __restrict__ atom_mask,
                const float* __restrict__ b1,
                const float* __restrict__ W2,
                const float* __restrict__ b2,
                const float* __restrict__ atomref,
                const float* __restrict__ mean,
                const float* __restrict__ stddev,
                float*       __restrict__ out) {
    __shared__ __align__(16) unsigned char smA[TILEB];
    __shared__ float red[8];

    const int tid  = threadIdx.x;
    const int w    = tid >> 5;          // warp 0..5
    const int lane = tid & 31;
    const int b    = blockIdx.x;

    const int rg = w >> 1;              // row group 0..2
    const int cg = w & 1;               // col group 0..1

    const int qr = lane >> 2;           // 0..7
    const int qc = lane & 3;            // 0..3
    const int r0 = rg * 32 + qr;        // rows r0, r0+8, r0+16, r0+24

    const float* xb = rep + (size_t)b * (NATOM * NIN);
    const uint32_t sbase = (uint32_t)__cvta_generic_to_shared(smA);

    // ---- fill: warp w loads rows [16w, 16w+16) coalesced, cvt fp16, swizzled STS ----
    {
        const float4* rowsrc = reinterpret_cast<const float4*>(xb + (w * 16) * NIN);
        #pragma unroll
        for (int rr = 0; rr < 16; rr += 8) {
            float4 v[8];
            #pragma unroll
            for (int j = 0; j < 8; j++)
                v[j] = __ldg(rowsrc + (rr + j) * 32 + lane);
            #pragma unroll
            for (int j = 0; j < 8; j++) {
                int r = w * 16 + rr + j;
                __half2 h0 = __floats2half2_rn(v[j].x, v[j].y);
                __half2 h1 = __floats2half2_rn(v[j].z, v[j].w);
                uint32_t u0 = *reinterpret_cast<uint32_t*>(&h0);
                uint32_t u1 = *reinterpret_cast<uint32_t*>(&h1);
                uint32_t off = (uint32_t)(r * ROWB + ((lane * 8) ^ (((r >> 3) & 1) << 4)));
                asm volatile("st.shared.v2.u32 [%0], {%1,%2};"
                             :: "r"(sbase + off), "r"(u0), "r"(u1));
            }
        }
    }
    __syncthreads();

    float acc[2][4][4];
    #pragma unroll
    for (int m = 0; m < 2; m++)
        #pragma unroll
        for (int nt = 0; nt < 4; nt++)
            #pragma unroll
            for (int r = 0; r < 4; r++) acc[m][nt][r] = 0.f;

    const uint32_t rsel = lane & 15;
    const uint32_t csel = (uint32_t)(lane >> 4) * 16;

    #pragma unroll
    for (int kt = 0; kt < 8; kt++) {
        uint32_t a0[4], a1[4];
        {
            uint32_t r = (uint32_t)(rg * 32) + rsel;
            uint32_t col = ((uint32_t)(kt * 32) + csel) ^ (((r >> 3) & 1) << 4);
            ldsm_x4(a0, sbase + r * ROWB + col);
        }
        {
            uint32_t r = (uint32_t)(rg * 32 + 16) + rsel;
            uint32_t col = ((uint32_t)(kt * 32) + csel) ^ (((r >> 3) & 1) << 4);
            ldsm_x4(a1, sbase + r * ROWB + col);
        }

        #pragma unroll
        for (int ntl = 0; ntl < 4; ntl++) {
            int ntg = cg * 4 + ntl;
            uint2 bb = __ldg(&g_wh[(ntg * 8 + kt) * 32 + lane]);  // L1-hit after warmup
            mma_f16(acc[0][ntl], a0, &bb.x);
            mma_f16(acc[1][ntl], a1, &bb.x);
        }
    }

    // ---- epilogue: lean ssp (lg2 space) + partial W2 dot over this warp's 32 cols ----
    float sum0 = 0.f, sum1 = 0.f, sum2 = 0.f, sum3 = 0.f;
    const int tg2 = qc * 2;
    #pragma unroll
    for (int ntl = 0; ntl < 4; ntl++) {
        int c0 = (cg * 4 + ntl) * 8 + tg2;
        float2 b1v = __ldg(reinterpret_cast<const float2*>(b1 + c0));
        float2 w2v = __ldg(reinterpret_cast<const float2*>(W2 + c0));
        float b1x = b1v.x * LOG2E, b1y = b1v.y * LOG2E;

        sum0 = fmaf(lg2f(fmaf(ex2f(fmaf(acc[0][ntl][0], LOG2E, b1x)), 0.5f, 0.5f)), w2v.x, sum0);
        sum0 = fmaf(lg2f(fmaf(ex2f(fmaf(acc[0][ntl][1], LOG2E, b1y)), 0.5f, 0.5f)), w2v.y, sum0);
        sum1 = fmaf(lg2f(fmaf(ex2f(fmaf(acc[0][ntl][2], LOG2E, b1x)), 0.5f, 0.5f)), w2v.x, sum1);
        sum1 = fmaf(lg2f(fmaf(ex2f(fmaf(acc[0][ntl][3], LOG2E, b1y)), 0.5f, 0.5f)), w2v.y, sum1);
        sum2 = fmaf(lg2f(fmaf(ex2f(fmaf(acc[1][ntl][0], LOG2E, b1x)), 0.5f, 0.5f)), w2v.x, sum2);
        sum2 = fmaf(lg2f(fmaf(ex2f(fmaf(acc[1][ntl][1], LOG2E, b1y)), 0.5f, 0.5f)), w2v.y, sum2);
        sum3 = fmaf(lg2f(fmaf(ex2f(fmaf(acc[1][ntl][2], LOG2E, b1x)), 0.5f, 0.5f)), w2v.x, sum3);
        sum3 = fmaf(lg2f(fmaf(ex2f(fmaf(acc[1][ntl][3], LOG2E, b1y)), 0.5f, 0.5f)), w2v.y, sum3);
    }
    sum0 += __shfl_xor_sync(0xffffffffu, sum0, 1);
    sum0 += __shfl_xor_sync(0xffffffffu, sum0, 2);
    sum1 += __shfl_xor_sync(0xffffffffu, sum1, 1);
    sum1 += __shfl_xor_sync(0xffffffffu, sum1, 2);
    sum2 += __shfl_xor_sync(0xffffffffu, sum2, 1);
    sum2 += __shfl_xor_sync(0xffffffffu, sum2, 2);
    sum3 += __shfl_xor_sync(0xffffffffu, sum3, 1);
    sum3 += __shfl_xor_sync(0xffffffffu, sum3, 2);

    // per-row finish: y_row = dot*std*mask + (b2*std+mean+aref)*mask, const on cg==0.
    // sums are in lg2 space -> scale by stddev*ln2.
    float contrib = 0.f;
    if (qc == 0) {
        float scStd  = stddev[0];
        float scStdL = scStd * LN2;
        float sv[4] = {sum0, sum1, sum2, sum3};
        float tot = 0.f;
        if (cg == 0) {
            float cbase = fmaf(b2[0], scStd, mean[0]);
            #pragma unroll
            for (int m = 0; m < 4; m++) {
                int g = b * NATOM + r0 + m * 8;
                float vv = fmaf(sv[m], scStdL, cbase + atomref[atomic_numbers[g]]);
                tot += vv * atom_mask[g];
            }
        } else {
            #pragma unroll
            for (int m = 0; m < 4; m++) {
                int g = b * NATOM + r0 + m * 8;
                tot += sv[m] * scStdL * atom_mask[g];
            }
        }
        contrib = tot;
    }
    contrib += __shfl_xor_sync(0xffffffffu, contrib, 4);
    contrib += __shfl_xor_sync(0xffffffffu, contrib, 8);
    contrib += __shfl_xor_sync(0xffffffffu, contrib, 16);

    if (lane == 0) red[w] = contrib;
    __syncthreads();
    if (tid == 0) {
        float s = red[0];
        #pragma unroll
        for (int i = 1; i < 6; i++) s += red[i];
        out[b] = s;
    }
}

// ---------------- host launch ----------------
extern "C" void kernel_launch(void* const* d_in, const int* in_sizes, int n_in,
                              void* d_out, int out_size) {
    const float* rep   = (const float*)d_in[0];
    const int*   zn    = (const int*)  d_in[1];
    const float* mask  = (const float*)d_in[2];
    const float* W1    = (const float*)d_in[3];
    const float* b1    = (const float*)d_in[4];
    const float* W2    = (const float*)d_in[5];
    const float* b2    = (const float*)d_in[6];
    const float* aref  = (const float*)d_in[7];
    const float* mean  = (const float*)d_in[8];
    const float* stdd  = (const float*)d_in[9];
    float* out = (float*)d_out;

    prep_w_kernel<<<32, 256>>>(W1);
    atomwise_kernel<<<BATCH, 192>>>(rep, zn, mask, b1, W2, b2, aref, mean, stdd, out);
}